// round 2
// baseline (speedup 1.0000x reference)
#include <cuda_runtime.h>
#include <cuda_bf16.h>

// out[b,o] = sum over UNIQUE keys k=i0*350+i1 in batch row b of W[k,o], + bias[o]
// (reference scatters 1.0 with .set, so duplicate hits count once)

#define B      32
#define NHITS  200
#define D1     350
#define OUTN   5
#define NT     256

__global__ __launch_bounds__(NT, 1)
void prtnn_kernel(const int* __restrict__ x,
                  const float* __restrict__ W,
                  const float* __restrict__ bias,
                  float* __restrict__ out)
{
    __shared__ int   keys[NHITS];
    __shared__ float acc[OUTN][NT];

    const int b = blockIdx.x;
    const int t = threadIdx.x;

    // Load this row's 200 keys (i0*350 + i1) into shared memory.
    if (t < NHITS) {
        const int* hit = x + ((long long)b * NHITS + t) * 3;
        keys[t] = hit[1] * D1 + hit[2];
    }
    __syncthreads();

    // Each hit thread: check for an earlier duplicate; if unique, gather W row.
    float c[OUTN] = {0.f, 0.f, 0.f, 0.f, 0.f};
    if (t < NHITS) {
        const int k = keys[t];
        bool dup = false;
        for (int j = 0; j < t; ++j) {
            if (keys[j] == k) { dup = true; break; }
        }
        if (!dup) {
            const float* w = W + (long long)k * OUTN;
            #pragma unroll
            for (int o = 0; o < OUTN; ++o) c[o] = __ldg(w + o);
        }
    }

    #pragma unroll
    for (int o = 0; o < OUTN; ++o) acc[o][t] = c[o];
    __syncthreads();

    // Deterministic fixed-pairing tree reduction over 256 slots.
    #pragma unroll
    for (int s = NT / 2; s > 32; s >>= 1) {
        if (t < s) {
            #pragma unroll
            for (int o = 0; o < OUTN; ++o) acc[o][t] += acc[o][t + s];
        }
        __syncthreads();
    }
    // Final 64->1 within one warp (still fixed pairing, deterministic).
    if (t < 32) {
        #pragma unroll
        for (int o = 0; o < OUTN; ++o) {
            float v = acc[o][t] + acc[o][t + 32];
            #pragma unroll
            for (int s = 16; s > 0; s >>= 1)
                v += __shfl_down_sync(0xFFFFFFFFu, v, s);
            if (t == 0) acc[o][0] = v;
        }
    }
    __syncthreads();

    if (t < OUTN) out[b * OUTN + t] = acc[t][0] + bias[t];
}

extern "C" void kernel_launch(void* const* d_in, const int* in_sizes, int n_in,
                              void* d_out, int out_size)
{
    const int*   x    = (const int*)d_in[0];    // [32, 200, 3] int32
    const float* W    = (const float*)d_in[1];  // [2150400, 5] f32
    const float* bias = (const float*)d_in[2];  // [5] f32
    float*       out  = (float*)d_out;          // [32, 5] f32

    prtnn_kernel<<<B, NT>>>(x, W, bias, out);
}

// round 3
// speedup vs baseline: 1.3538x; 1.3538x over previous
#include <cuda_runtime.h>
#include <cuda_bf16.h>

// out[b,o] = sum over UNIQUE keys k=i0*350+i1 in batch row b of W[k,o], + bias[o]
// (reference scatters 1.0 with .set, so duplicate hits count once)

#define B      32
#define NHITS  200
#define D1     350
#define OUTN   5
#define NT     256
#define NW     (NT / 32)
#define HSZ    512          // hash table slots (power of two)
#define HMASK  (HSZ - 1)
#define EMPTY  (-1)

__global__ __launch_bounds__(NT, 1)
void prtnn_kernel(const int* __restrict__ x,
                  const float* __restrict__ W,
                  const float* __restrict__ bias,
                  float* __restrict__ out)
{
    __shared__ int   tab[HSZ];
    __shared__ float wacc[NW][OUTN];

    const int b = blockIdx.x;
    const int t = threadIdx.x;
    const int wid = t >> 5;
    const int lid = t & 31;

    // Kick off the scattered x loads immediately (longest-latency leaf).
    int k = 0;
    if (t < NHITS) {
        const int* hit = x + ((long long)b * NHITS + t) * 3;
        k = hit[1] * D1 + hit[2];          // 0 .. 2150399
    }

    // Init hash table in parallel with the x loads (independent work).
    #pragma unroll
    for (int i = t; i < HSZ; i += NT) tab[i] = EMPTY;
    __syncthreads();

    // O(1) dedup: exactly one thread per distinct key wins the CAS.
    // The winning thread's identity is schedule-dependent, but the SET of
    // unique keys (and thus the gathered sum) is not.
    bool unique = false;
    if (t < NHITS) {
        unsigned h = ((unsigned)k * 2654435761u) >> 20;   // golden-ratio hash
        h &= HMASK;
        while (true) {
            int old = atomicCAS(&tab[h], EMPTY, k);
            if (old == EMPTY) { unique = true; break; }   // inserted: winner
            if (old == k)     { break; }                  // already present: dup
            h = (h + 1) & HMASK;                          // linear probe
        }
    }

    // Gather the 5-float W row for unique keys. 20B contiguous per thread,
    // scattered across W; ~200 independent loads -> high MLP, one DRAM round.
    float c[OUTN] = {0.f, 0.f, 0.f, 0.f, 0.f};
    if (unique) {
        const float* w = W + (long long)k * OUTN;
        #pragma unroll
        for (int o = 0; o < OUTN; ++o) c[o] = __ldg(w + o);
    }

    // Per-warp fixed-pairing shuffle reduction (deterministic).
    #pragma unroll
    for (int o = 0; o < OUTN; ++o) {
        float v = c[o];
        #pragma unroll
        for (int s = 16; s > 0; s >>= 1)
            v += __shfl_down_sync(0xFFFFFFFFu, v, s);
        if (lid == 0) wacc[wid][o] = v;
    }
    __syncthreads();

    // Final 8-way sum, fixed order, by 5 threads.
    if (t < OUTN) {
        float v = bias[t];
        #pragma unroll
        for (int w = 0; w < NW; ++w) v += wacc[w][t];
        out[b * OUTN + t] = v;
    }
}

extern "C" void kernel_launch(void* const* d_in, const int* in_sizes, int n_in,
                              void* d_out, int out_size)
{
    const int*   x    = (const int*)d_in[0];    // [32, 200, 3] int32
    const float* W    = (const float*)d_in[1];  // [2150400, 5] f32
    const float* bias = (const float*)d_in[2];  // [5] f32
    float*       out  = (float*)d_out;          // [32, 5] f32

    prtnn_kernel<<<B, NT>>>(x, W, bias, out);
}